// round 13
// baseline (speedup 1.0000x reference)
#include <cuda_runtime.h>
#include <cuda_fp16.h>
#include <stdint.h>
#include <math.h>

// Problem constants: B=2, N=2048 -> T=4096 tokens, D=1024, E=8, H=2048, K=2
#define Tn 4096
#define Dd 1024
#define Ee 8
#define Hh 2048

// ---- tf32 core config (verified R10, 546us) ----
#define BM 128
#define BN 128
#define BK 16
#define STAGES 3
#define ASTR 20                       // A smem row stride (floats)
#define BSTR 136                      // B smem row stride (floats)
#define ASZ (BM * ASTR)               // 2560 floats / stage
#define BSZ (BK * BSTR)               // 2176 floats / stage
#define SMEM_FLOATS (STAGES * (ASZ + BSZ))   // 14208 floats = 56832 B

// ---- fp16 shadow core config (R12 under test) ----
#define HBK 32
#define HBKP 16
#define HASTRW 20
#define HBNPW 136
#define HASZW (BM * HASTRW)           // 2560 words
#define HBSZW (HBKP * HBNPW)          // 2176 words
#define HABASE (STAGES * HASZW)
#define SMEM_WORDS (STAGES * (HASZW + HBSZW))  // 14208 words = 56832 B

// ---------------- device scratch (allocation-free rule: __device__ globals) --
__device__ int     g_cnt[Ee];
__device__ int     g_bad;                         // fp16-vs-tf32 mismatch flag
__device__ int     g_list[Ee * Tn];
__device__ float   g_gate[Tn * 2];
__device__ float   g_ent[Tn];
// tf32 pipeline buffers
__device__ float   g_h[(size_t)Ee * Tn * Hh];
__device__ float   g_y[(size_t)Tn * 2 * Dd];
__device__ float   g_xt[(size_t)Tn * Dd];
__device__ float   g_w1r[(size_t)Ee * Dd * Hh];
__device__ float   g_w2r[(size_t)Ee * Hh * Dd];
// fp16 shadow buffers
__device__ __half  g_hh[(size_t)Ee * Tn * Hh];
__device__ float   g_yh[(size_t)Tn * 2 * Dd];
__device__ __half  g_xh[(size_t)Tn * Dd];
__device__ __half2 g_w1p[(size_t)Ee * (Dd / 2) * Hh];
__device__ __half2 g_w2p[(size_t)Ee * (Hh / 2) * Dd];

// -------------------------------------------------------------- helpers -----
__device__ __forceinline__ float f2tf_f(float x) {
    uint32_t r;
    asm("cvt.rna.tf32.f32 %0, %1;" : "=r"(r) : "f"(x));
    return __uint_as_float(r);
}
__device__ __forceinline__ void cp16f(float* s, const float* g) {
    uint32_t sa = (uint32_t)__cvta_generic_to_shared(s);
    asm volatile("cp.async.cg.shared.global [%0], [%1], 16;" :: "r"(sa), "l"(g));
}
__device__ __forceinline__ void cp16w(uint32_t* s, const void* g) {
    uint32_t sa = (uint32_t)__cvta_generic_to_shared(s);
    asm volatile("cp.async.cg.shared.global [%0], [%1], 16;" :: "r"(sa), "l"(g));
}
__device__ __forceinline__ void mma8(float* c, const uint32_t* a, const uint32_t* b) {
    asm volatile(
        "mma.sync.aligned.m16n8k8.row.col.f32.tf32.tf32.f32 "
        "{%0,%1,%2,%3}, {%4,%5,%6,%7}, {%8,%9}, {%0,%1,%2,%3};"
        : "+f"(c[0]), "+f"(c[1]), "+f"(c[2]), "+f"(c[3])
        : "r"(a[0]), "r"(a[1]), "r"(a[2]), "r"(a[3]), "r"(b[0]), "r"(b[1]));
}
__device__ __forceinline__ void mma16(float* c, const uint32_t* a, const uint32_t* b) {
    asm volatile(
        "mma.sync.aligned.m16n8k16.row.col.f32.f16.f16.f32 "
        "{%0,%1,%2,%3}, {%4,%5,%6,%7}, {%8,%9}, {%0,%1,%2,%3};"
        : "+f"(c[0]), "+f"(c[1]), "+f"(c[2]), "+f"(c[3])
        : "r"(a[0]), "r"(a[1]), "r"(a[2]), "r"(a[3]), "r"(b[0]), "r"(b[1]));
}

// ---------------------------------------------------------------- init ------
__global__ void init_kernel() {
    if (threadIdx.x < Ee) g_cnt[threadIdx.x] = 0;
    if (threadIdx.x == 31) g_bad = 0;
}

// ------------------------------------------------------------- routing ------
__global__ void routing_kernel(const float* __restrict__ x,
                               const float* __restrict__ wg,
                               const float* __restrict__ bg) {
    const int t    = blockIdx.x * 8 + (threadIdx.x >> 5);
    const int lane = threadIdx.x & 31;
    if (t >= Tn) return;

    float acc[Ee];
#pragma unroll
    for (int e = 0; e < Ee; e++) acc[e] = 0.f;

    const float* xr = x + (size_t)t * Dd;
    for (int c = lane; c < Dd; c += 32) {
        const float xv = xr[c];
        const float4* w4 = reinterpret_cast<const float4*>(wg + (size_t)c * Ee);
        const float4 a = w4[0];
        const float4 b = w4[1];
        acc[0] += xv * a.x; acc[1] += xv * a.y; acc[2] += xv * a.z; acc[3] += xv * a.w;
        acc[4] += xv * b.x; acc[5] += xv * b.y; acc[6] += xv * b.z; acc[7] += xv * b.w;
    }
#pragma unroll
    for (int off = 16; off; off >>= 1) {
#pragma unroll
        for (int e = 0; e < Ee; e++)
            acc[e] += __shfl_xor_sync(0xffffffffu, acc[e], off);
    }

    if (lane == 0) {
        float l[Ee];
#pragma unroll
        for (int e = 0; e < Ee; e++) l[e] = acc[e] + bg[e];

        int i0 = 0; float v0 = l[0];
#pragma unroll
        for (int e = 1; e < Ee; e++) if (l[e] > v0) { v0 = l[e]; i0 = e; }
        int i1 = -1; float v1 = -3.4e38f;
#pragma unroll
        for (int e = 0; e < Ee; e++)
            if (e != i0 && l[e] > v1) { v1 = l[e]; i1 = e; }

        const float e1 = expf(v1 - v0);
        const float inv = 1.f / (1.f + e1);
        const float gv0 = inv;
        const float gv1 = e1 * inv;

        g_ent[t] = -(gv0 * logf(fmaxf(gv0, 1e-8f)) +
                     gv1 * logf(fmaxf(gv1, 1e-8f)));

        int p0 = atomicAdd(&g_cnt[i0], 1);
        g_list[i0 * Tn + p0] = t * 2 + 0;
        g_gate[t * 2 + 0] = gv0;

        int p1 = atomicAdd(&g_cnt[i1], 1);
        g_list[i1 * Tn + p1] = t * 2 + 1;
        g_gate[t * 2 + 1] = gv1;
    }
}

// ------------------------------------------------- entropy (deterministic) --
__global__ void entropy_kernel(float* __restrict__ out, int do_write) {
    __shared__ float sh[1024];
    const int t = threadIdx.x;
    float s = 0.f;
    for (int i = t; i < Tn; i += 1024) s += g_ent[i];
    sh[t] = s;
    __syncthreads();
    for (int o = 512; o; o >>= 1) {
        if (t < o) sh[t] += sh[t + o];
        __syncthreads();
    }
    if (t == 0 && do_write) out[(size_t)Tn * Dd] = sh[0] / (float)Tn;
}

// --------------------------------------------- tf32 pre-round (verified) ----
__global__ void round_x_kernel(const float* __restrict__ x) {
    const int idx = blockIdx.x * 256 + threadIdx.x;
    float4 v = ((const float4*)x)[idx];
    v.x = f2tf_f(v.x); v.y = f2tf_f(v.y); v.z = f2tf_f(v.z); v.w = f2tf_f(v.w);
    ((float4*)g_xt)[idx] = v;
}
__global__ void round_w1_kernel(const float* __restrict__ w1) {
    const size_t idx = (size_t)blockIdx.x * 256 + threadIdx.x;
    float4 v = ((const float4*)w1)[idx];
    v.x = f2tf_f(v.x); v.y = f2tf_f(v.y); v.z = f2tf_f(v.z); v.w = f2tf_f(v.w);
    ((float4*)g_w1r)[idx] = v;
}
__global__ void round_w2_kernel(const float* __restrict__ w2) {
    const size_t idx = (size_t)blockIdx.x * 256 + threadIdx.x;
    float4 v = ((const float4*)w2)[idx];
    v.x = f2tf_f(v.x); v.y = f2tf_f(v.y); v.z = f2tf_f(v.z); v.w = f2tf_f(v.w);
    ((float4*)g_w2r)[idx] = v;
}

// ------------------------------------------------------ fp16 pre-pass -------
__global__ void half_x_kernel(const float* __restrict__ x) {
    const int idx = blockIdx.x * 256 + threadIdx.x;
    float4 v = ((const float4*)x)[idx];
    __half2* o = (__half2*)g_xh;
    o[idx * 2 + 0] = __floats2half2_rn(v.x, v.y);
    o[idx * 2 + 1] = __floats2half2_rn(v.z, v.w);
}
__global__ void pack_w_kernel(const float* __restrict__ w,
                              __half2* __restrict__ wp, int K, int N) {
    const unsigned idx  = blockIdx.x * 256 + threadIdx.x;
    const unsigned perE = (unsigned)(K / 2) * (unsigned)N;
    const unsigned e    = idx / perE;
    const unsigned kn   = idx % perE;
    const unsigned kp   = kn / (unsigned)N;
    const unsigned n    = kn % (unsigned)N;
    const float* we = w + (size_t)e * K * N;
    const float lo = we[(size_t)(2 * kp) * N + n];
    const float hi = we[(size_t)(2 * kp + 1) * N + n];
    wp[idx] = __floats2half2_rn(lo, hi);
}

// ------------------------------------- tf32 grouped GEMM (verified R10) -----
template<int N, int KD, bool G1>
__global__ __launch_bounds__(256, 2)
void moe_gemm_t(const float* __restrict__ bias)
{
    const int e    = blockIdx.z;
    const int cnt  = g_cnt[e];
    const int row0 = blockIdx.x * BM;
    if (row0 >= cnt) return;
    const int col0 = blockIdx.y * BN;

    extern __shared__ float sm[];
    float* As = sm;
    float* Bs = sm + STAGES * ASZ;

    const int tid  = threadIdx.x;
    const int lane = tid & 31;
    const int warp = tid >> 5;
    const int wm   = warp & 1;
    const int wn   = warp >> 1;

    const int ar0 = tid >> 2;
    const int ak4 = (tid & 3) * 4;
    const float* ap0;
    const float* ap1;
    if (G1) {
        const int t0 = g_list[e * Tn + row0 + ar0] >> 1;
        const int t1 = g_list[e * Tn + row0 + ar0 + 64] >> 1;
        ap0 = g_xt + (size_t)t0 * KD + ak4;
        ap1 = g_xt + (size_t)t1 * KD + ak4;
    } else {
        ap0 = g_h + ((size_t)e * Tn + row0 + ar0) * KD + ak4;
        ap1 = g_h + ((size_t)e * Tn + row0 + ar0 + 64) * KD + ak4;
    }

    const int brow = tid >> 5;
    const int bc4  = lane * 4;
    const float* W = G1 ? g_w1r : g_w2r;
    const float* Wp = W + (size_t)e * KD * N + col0 + bc4;

    float acc[4][4][4];
#pragma unroll
    for (int mi = 0; mi < 4; mi++)
#pragma unroll
        for (int ni = 0; ni < 4; ni++)
#pragma unroll
            for (int j = 0; j < 4; j++) acc[mi][ni][j] = 0.f;

    auto load_stage = [&](int s, int kt) {
        float* as = As + s * ASZ;
        float* bs = Bs + s * BSZ;
        const int kg = kt * BK;
        cp16f(as + ar0 * ASTR + ak4, ap0 + kg);
        cp16f(as + (ar0 + 64) * ASTR + ak4, ap1 + kg);
        cp16f(bs + brow * BSTR + bc4,       Wp + (size_t)(kg + brow) * N);
        cp16f(bs + (brow + 8) * BSTR + bc4, Wp + (size_t)(kg + brow + 8) * N);
    };

    auto compute = [&](int s) {
        const float* as = As + s * ASZ;
        const float* bs = Bs + s * BSZ;
#pragma unroll
        for (int g = 0; g < 2; g++) {
            uint32_t Af[4][4];
#pragma unroll
            for (int mi = 0; mi < 4; mi++) {
                const int r = wm * 64 + mi * 16 + (lane >> 2);
                const int k = g * 8 + (lane & 3);
                const float* p = as + r * ASTR + k;
                Af[mi][0] = __float_as_uint(p[0]);
                Af[mi][1] = __float_as_uint(p[8 * ASTR]);
                Af[mi][2] = __float_as_uint(p[4]);
                Af[mi][3] = __float_as_uint(p[8 * ASTR + 4]);
            }
            uint32_t Bf[4][2];
#pragma unroll
            for (int ni = 0; ni < 4; ni++) {
                const int c = wn * 32 + ni * 8 + (lane >> 2);
                const int k = g * 8 + (lane & 3);
                const float* p = bs + k * BSTR + c;
                Bf[ni][0] = __float_as_uint(p[0]);
                Bf[ni][1] = __float_as_uint(p[4 * BSTR]);
            }
#pragma unroll
            for (int mi = 0; mi < 4; mi++)
#pragma unroll
                for (int ni = 0; ni < 4; ni++)
                    mma8(acc[mi][ni], Af[mi], Bf[ni]);
        }
    };

    constexpr int KT = KD / BK;
#pragma unroll
    for (int s = 0; s < STAGES - 1; s++) {
        load_stage(s, s);
        asm volatile("cp.async.commit_group;");
    }
    for (int kt = 0; kt < KT; kt++) {
        asm volatile("cp.async.wait_group 1;" ::: "memory");
        __syncthreads();
        const int nt = kt + STAGES - 1;
        if (nt < KT) load_stage(nt % STAGES, nt);
        asm volatile("cp.async.commit_group;");
        compute(kt % STAGES);
    }

    const float* bp = bias + (size_t)e * N + col0;
    float2 bv[4];
#pragma unroll
    for (int ni = 0; ni < 4; ni++) {
        const int c = wn * 32 + ni * 8 + 2 * (lane & 3);
        bv[ni] = *(const float2*)(bp + c);
    }
#pragma unroll
    for (int mi = 0; mi < 4; mi++) {
#pragma unroll
        for (int h = 0; h < 2; h++) {
            const int r = row0 + wm * 64 + mi * 16 + (lane >> 2) + h * 8;
            if (r >= cnt) continue;
            float* op;
            if (G1) op = g_h + ((size_t)e * Tn + r) * N;
            else    op = g_y + (size_t)g_list[e * Tn + r] * N;
#pragma unroll
            for (int ni = 0; ni < 4; ni++) {
                const int c = col0 + wn * 32 + ni * 8 + 2 * (lane & 3);
                float v0 = acc[mi][ni][h * 2 + 0] + bv[ni].x;
                float v1 = acc[mi][ni][h * 2 + 1] + bv[ni].y;
                if (G1) {
                    v0 = f2tf_f(fmaxf(v0, 0.f));
                    v1 = f2tf_f(fmaxf(v1, 0.f));
                }
                *(float2*)(op + c) = make_float2(v0, v1);
            }
        }
    }
}

// ------------------------------------- fp16 grouped GEMM (R12, under test) --
template<int NOUT, int KD, bool G1>
__global__ __launch_bounds__(256, 2)
void moe_gemm_h(const float* __restrict__ bias)
{
    const int e    = blockIdx.z;
    const int cnt  = g_cnt[e];
    const int row0 = blockIdx.x * BM;
    if (row0 >= cnt) return;
    const int col0 = blockIdx.y * BN;

    extern __shared__ uint32_t smw[];

    const int tid  = threadIdx.x;
    const int lane = tid & 31;
    const int warp = tid >> 5;
    const int wm   = warp & 1;
    const int wn   = warp >> 1;

    const int ar0 = tid >> 2;
    const int ak  = tid & 3;
    const __half* ap0;
    const __half* ap1;
    if (G1) {
        const int t0 = g_list[e * Tn + row0 + ar0] >> 1;
        const int t1 = g_list[e * Tn + row0 + ar0 + 64] >> 1;
        ap0 = g_xh + (size_t)t0 * KD;
        ap1 = g_xh + (size_t)t1 * KD;
    } else {
        ap0 = g_hh + ((size_t)e * Tn + row0 + ar0) * KD;
        ap1 = g_hh + ((size_t)e * Tn + row0 + ar0 + 64) * KD;
    }

    const int brow = tid >> 5;
    const __half2* Wp = (G1 ? g_w1p : g_w2p)
                        + (size_t)e * (KD / 2) * NOUT + col0;

    float acc[4][4][4];
#pragma unroll
    for (int mi = 0; mi < 4; mi++)
#pragma unroll
        for (int ni = 0; ni < 4; ni++)
#pragma unroll
            for (int j = 0; j < 4; j++) acc[mi][ni][j] = 0.f;

    auto load_stage = [&](int s, int kt) {
        uint32_t* as = smw + s * HASZW;
        uint32_t* bs = smw + HABASE + s * HBSZW;
        cp16w(as + ar0 * HASTRW + ak * 4,        ap0 + kt * HBK + ak * 8);
        cp16w(as + (ar0 + 64) * HASTRW + ak * 4, ap1 + kt * HBK + ak * 8);
        cp16w(bs + brow * HBNPW + lane * 4,
              Wp + (size_t)(kt * HBKP + brow) * NOUT + lane * 4);
        cp16w(bs + (brow + 8) * HBNPW + lane * 4,
              Wp + (size_t)(kt * HBKP + brow + 8) * NOUT + lane * 4);
    };

    auto compute = [&](int s) {
        const uint32_t* as = smw + s * HASZW;
        const uint32_t* bs = smw + HABASE + s * HBSZW;
#pragma unroll
        for (int g = 0; g < 2; g++) {
            const int kq = g * 8 + (lane & 3);
            uint32_t Af[4][4];
#pragma unroll
            for (int mi = 0; mi < 4; mi++) {
                const int r = wm * 64 + mi * 16 + (lane >> 2);
                Af[mi][0] = as[r * HASTRW + kq];
                Af[mi][1] = as[(r + 8) * HASTRW + kq];
                Af[mi][2] = as[r * HASTRW + kq + 4];
                Af[mi][3] = as[(r + 8) * HASTRW + kq + 4];
            }
            uint32_t Bf[4][2];
#pragma unroll
            for (int ni = 0; ni < 4; ni++) {
                const int n = wn * 32 + ni * 8 + (lane >> 2);
                Bf[ni][0] = bs[kq * HBNPW + n];
                Bf[ni][1] = bs[(kq + 4) * HBNPW + n];
            }
#pragma unroll
            for (int mi = 0; mi < 4; mi++)
#pragma unroll
                for (int ni = 0; ni < 4; ni++)
                    mma16(acc[mi][ni], Af[mi], Bf[ni]);
        }
    };

    constexpr int KT = KD / HBK;
#pragma unroll
    for (int s = 0; s < STAGES - 1; s++) {
        load_stage(s, s);
        asm volatile("cp.async.commit_group;");
    }
    for (int kt = 0; kt < KT; kt++) {
        asm volatile("cp.async.wait_group 1;" ::: "memory");
        __syncthreads();
        const int nt = kt + STAGES - 1;
        if (nt < KT) load_stage(nt % STAGES, nt);
        asm volatile("cp.async.commit_group;");
        compute(kt % STAGES);
    }

    const float* bp = bias + (size_t)e * NOUT + col0;
    float2 bv[4];
#pragma unroll
    for (int ni = 0; ni < 4; ni++) {
        const int c = wn * 32 + ni * 8 + 2 * (lane & 3);
        bv[ni] = *(const float2*)(bp + c);
    }
#pragma unroll
    for (int mi = 0; mi < 4; mi++) {
#pragma unroll
        for (int h = 0; h < 2; h++) {
            const int r = row0 + wm * 64 + mi * 16 + (lane >> 2) + h * 8;
            if (r >= cnt) continue;
#pragma unroll
            for (int ni = 0; ni < 4; ni++) {
                const int c = col0 + wn * 32 + ni * 8 + 2 * (lane & 3);
                float v0 = acc[mi][ni][h * 2 + 0] + bv[ni].x;
                float v1 = acc[mi][ni][h * 2 + 1] + bv[ni].y;
                if (G1) {
                    __half* op = g_hh + ((size_t)e * Tn + r) * NOUT;
                    *(__half2*)(op + c) =
                        __floats2half2_rn(fmaxf(v0, 0.f), fmaxf(v1, 0.f));
                } else {
                    float* op = g_yh + (size_t)g_list[e * Tn + r] * NOUT;
                    *(float2*)(op + c) = make_float2(v0, v1);
                }
            }
        }
    }
}

// ------------------------- shadow check: g_yh vs g_y (deterministic) --------
__global__ void check_kernel() {
    const int idx = blockIdx.x * 256 + threadIdx.x;    // over Tn*2*Dd/4
    const float4 a = ((const float4*)g_yh)[idx];
    const float4 b = ((const float4*)g_y)[idx];
    bool bad = (fabsf(a.x - b.x) > 0.05f + 0.05f * fabsf(b.x)) ||
               (fabsf(a.y - b.y) > 0.05f + 0.05f * fabsf(b.y)) ||
               (fabsf(a.z - b.z) > 0.05f + 0.05f * fabsf(b.z)) ||
               (fabsf(a.w - b.w) > 0.05f + 0.05f * fabsf(b.w));
    if (__any_sync(0xffffffffu, bad) && (threadIdx.x & 31) == 0)
        atomicOr(&g_bad, 1);
}

// ------------------------------- gated combine with shadow selection --------
__global__ void combine_kernel(float* __restrict__ out) {
    const int idx = blockIdx.x * 256 + threadIdx.x;
    const int t   = idx / (Dd / 4);
    const int c   = idx % (Dd / 4);
    const float gA = g_gate[2 * t];
    const float gB = g_gate[2 * t + 1];
    const float4* y4 = (const float4*)(g_bad ? g_y : g_yh);
    const float4 ya = y4[(size_t)(2 * t) * (Dd / 4) + c];
    const float4 yb = y4[(size_t)(2 * t + 1) * (Dd / 4) + c];
    float4 o;
    o.x = gA * ya.x + gB * yb.x;
    o.y = gA * ya.y + gB * yb.y;
    o.z = gA * ya.z + gB * yb.z;
    o.w = gA * ya.w + gB * yb.w;
    ((float4*)out)[idx] = o;
}

// ---------------------------------------------------------------- launch ----
extern "C" void kernel_launch(void* const* d_in, const int* in_sizes, int n_in,
                              void* d_out, int out_size) {
    const float* x  = (const float*)d_in[0];
    const float* wg = (const float*)d_in[1];
    const float* bg = (const float*)d_in[2];
    const float* w1 = (const float*)d_in[3];
    const float* b1 = (const float*)d_in[4];
    const float* w2 = (const float*)d_in[5];
    const float* b2 = (const float*)d_in[6];
    float* out = (float*)d_out;

    const int smem_t = SMEM_FLOATS * (int)sizeof(float);   // 56832
    const int smem_h = SMEM_WORDS * 4;                     // 56832
    cudaFuncSetAttribute(moe_gemm_t<Hh, Dd, true>,
                         cudaFuncAttributeMaxDynamicSharedMemorySize, smem_t);
    cudaFuncSetAttribute(moe_gemm_t<Dd, Hh, false>,
                         cudaFuncAttributeMaxDynamicSharedMemorySize, smem_t);
    cudaFuncSetAttribute(moe_gemm_h<Hh, Dd, true>,
                         cudaFuncAttributeMaxDynamicSharedMemorySize, smem_h);
    cudaFuncSetAttribute(moe_gemm_h<Dd, Hh, false>,
                         cudaFuncAttributeMaxDynamicSharedMemorySize, smem_h);

    init_kernel<<<1, 32>>>();
    routing_kernel<<<Tn / 8, 256>>>(x, wg, bg);
    entropy_kernel<<<1, 1024>>>(out, (out_size > Tn * Dd) ? 1 : 0);

    // ---- verified tf32 pipeline (safety net) ----
    round_x_kernel<<<(Tn * Dd / 4) / 256, 256>>>(x);
    round_w1_kernel<<<(int)(((size_t)Ee * Dd * Hh / 4) / 256), 256>>>(w1);
    round_w2_kernel<<<(int)(((size_t)Ee * Hh * Dd / 4) / 256), 256>>>(w2);
    moe_gemm_t<Hh, Dd, true><<<dim3(Tn / BM, Hh / BN, Ee), 256, smem_t>>>(b1);
    moe_gemm_t<Dd, Hh, false><<<dim3(Tn / BM, Dd / BN, Ee), 256, smem_t>>>(b2);

    // ---- fp16 shadow pipeline (under test) ----
    half_x_kernel<<<(Tn * Dd / 4) / 256, 256>>>(x);
    pack_w_kernel<<<(int)(((size_t)Ee * (Dd / 2) * Hh) / 256), 256>>>(w1, g_w1p, Dd, Hh);
    pack_w_kernel<<<(int)(((size_t)Ee * (Hh / 2) * Dd) / 256), 256>>>(w2, g_w2p, Hh, Dd);
    moe_gemm_h<Hh, Dd, true><<<dim3(Tn / BM, Hh / BN, Ee), 256, smem_h>>>(b1);
    moe_gemm_h<Dd, Hh, false><<<dim3(Tn / BM, Dd / BN, Ee), 256, smem_h>>>(b2);

    // ---- compare & select ----
    check_kernel<<<(Tn * 2 * Dd / 4) / 256, 256>>>();
    combine_kernel<<<(Tn * Dd / 4) / 256, 256>>>(out);
}

// round 15
// speedup vs baseline: 2.1193x; 2.1193x over previous
#include <cuda_runtime.h>
#include <stdint.h>
#include <math.h>

// Problem constants: B=2, N=2048 -> T=4096 tokens, D=1024, E=8, H=2048, K=2
#define Tn 4096
#define Dd 1024
#define Ee 8
#define Hh 2048

// GEMM tile config: block 128x128, BK=32, 8 warps (2m x 4n), warp tile 64x32,
// 3-stage cp.async, 2 CTAs/SM. B loaded as raw fp32 (weights), rna-rounded to
// tf32 in-register; A pre-rounded in gmem.
#define BM 128
#define BN 128
#define BK 32
#define STAGES 3
#define ASTR 36                      // A smem row stride (floats): 32 + 4 pad
#define BSTR 136                     // B smem row stride (floats): 128 + 8 pad
#define ASZ (BM * ASTR)              // 4608 floats / stage
#define BSZ (BK * BSTR)              // 4352 floats / stage
#define SMEM_FLOATS (STAGES * (ASZ + BSZ))   // 26880 floats = 107520 B

// ---------------- device scratch (allocation-free rule: __device__ globals) --
__device__ int   g_cnt[Ee];
__device__ int   g_list[Ee * Tn];            // pair slot (= token*2 + k) per expert row
__device__ float g_gate[Tn * 2];
__device__ float g_ent[Tn];
__device__ float g_h[(size_t)Ee * Tn * Hh];  // hidden activations (tf32-rounded)
__device__ float g_y[(size_t)Tn * 2 * Dd];   // per-pair expert outputs
__device__ float g_xt[(size_t)Tn * Dd];      // x, tf32-rounded (same layout)

// -------------------------------------------------------------- helpers -----
__device__ __forceinline__ float f2tf_f(float x) {
    uint32_t r;
    asm("cvt.rna.tf32.f32 %0, %1;" : "=r"(r) : "f"(x));
    return __uint_as_float(r);
}
__device__ __forceinline__ uint32_t f2tf_u(float x) {
    uint32_t r;
    asm("cvt.rna.tf32.f32 %0, %1;" : "=r"(r) : "f"(x));
    return r;
}
__device__ __forceinline__ void cp16f(float* s, const float* g) {
    uint32_t sa = (uint32_t)__cvta_generic_to_shared(s);
    asm volatile("cp.async.cg.shared.global [%0], [%1], 16;" :: "r"(sa), "l"(g));
}
__device__ __forceinline__ void mma8(float* c, const uint32_t* a, const uint32_t* b) {
    asm volatile(
        "mma.sync.aligned.m16n8k8.row.col.f32.tf32.tf32.f32 "
        "{%0,%1,%2,%3}, {%4,%5,%6,%7}, {%8,%9}, {%0,%1,%2,%3};"
        : "+f"(c[0]), "+f"(c[1]), "+f"(c[2]), "+f"(c[3])
        : "r"(a[0]), "r"(a[1]), "r"(a[2]), "r"(a[3]), "r"(b[0]), "r"(b[1]));
}

// ---------------------------------------------------------------- init ------
__global__ void init_kernel() {
    if (threadIdx.x < Ee) g_cnt[threadIdx.x] = 0;
}

// ------------------------------------------------------------- routing ------
__global__ void routing_kernel(const float* __restrict__ x,
                               const float* __restrict__ wg,
                               const float* __restrict__ bg) {
    const int t    = blockIdx.x * 8 + (threadIdx.x >> 5);
    const int lane = threadIdx.x & 31;
    if (t >= Tn) return;

    float acc[Ee];
#pragma unroll
    for (int e = 0; e < Ee; e++) acc[e] = 0.f;

    const float* xr = x + (size_t)t * Dd;
    for (int c = lane; c < Dd; c += 32) {
        const float xv = xr[c];
        const float4* w4 = reinterpret_cast<const float4*>(wg + (size_t)c * Ee);
        const float4 a = w4[0];
        const float4 b = w4[1];
        acc[0] += xv * a.x; acc[1] += xv * a.y; acc[2] += xv * a.z; acc[3] += xv * a.w;
        acc[4] += xv * b.x; acc[5] += xv * b.y; acc[6] += xv * b.z; acc[7] += xv * b.w;
    }
#pragma unroll
    for (int off = 16; off; off >>= 1) {
#pragma unroll
        for (int e = 0; e < Ee; e++)
            acc[e] += __shfl_xor_sync(0xffffffffu, acc[e], off);
    }

    if (lane == 0) {
        float l[Ee];
#pragma unroll
        for (int e = 0; e < Ee; e++) l[e] = acc[e] + bg[e];

        // top-2 (ties -> lowest index, matching jax.lax.top_k)
        int i0 = 0; float v0 = l[0];
#pragma unroll
        for (int e = 1; e < Ee; e++) if (l[e] > v0) { v0 = l[e]; i0 = e; }
        int i1 = -1; float v1 = -3.4e38f;
#pragma unroll
        for (int e = 0; e < Ee; e++)
            if (e != i0 && l[e] > v1) { v1 = l[e]; i1 = e; }

        const float e1 = expf(v1 - v0);
        const float inv = 1.f / (1.f + e1);
        const float gv0 = inv;
        const float gv1 = e1 * inv;

        g_ent[t] = -(gv0 * logf(fmaxf(gv0, 1e-8f)) +
                     gv1 * logf(fmaxf(gv1, 1e-8f)));

        int p0 = atomicAdd(&g_cnt[i0], 1);
        g_list[i0 * Tn + p0] = t * 2 + 0;
        g_gate[t * 2 + 0] = gv0;

        int p1 = atomicAdd(&g_cnt[i1], 1);
        g_list[i1 * Tn + p1] = t * 2 + 1;
        g_gate[t * 2 + 1] = gv1;
    }
}

// ------------------------------------------------- entropy (deterministic) --
__global__ void entropy_kernel(float* __restrict__ out, int do_write) {
    __shared__ float sh[1024];
    const int t = threadIdx.x;
    float s = 0.f;
    for (int i = t; i < Tn; i += 1024) s += g_ent[i];
    sh[t] = s;
    __syncthreads();
    for (int o = 512; o; o >>= 1) {
        if (t < o) sh[t] += sh[t + o];
        __syncthreads();
    }
    if (t == 0 && do_write) out[(size_t)Tn * Dd] = sh[0] / (float)Tn;
}

// --------------------------------------------- tf32 pre-round: x only -------
__global__ void round_x_kernel(const float* __restrict__ x) {
    const int idx = blockIdx.x * 256 + threadIdx.x;       // over Tn*Dd/4
    float4 v = ((const float4*)x)[idx];
    v.x = f2tf_f(v.x); v.y = f2tf_f(v.y); v.z = f2tf_f(v.z); v.w = f2tf_f(v.w);
    ((float4*)g_xt)[idx] = v;
}

// ----------------------------------------------------- tf32 grouped GEMM ----
// C[r, c] = A[r, :] @ W_e[:, c] + bias_e[c]   (relu+round+gather if G1,
// scatter-to-pair-slot if !G1). A pre-rounded tf32 bits; W raw fp32 from the
// input tensor, rna-rounded in-register at fragment load.
template<int N, int KD, bool G1>
__global__ __launch_bounds__(256, 2)
void moe_gemm(const float* __restrict__ W, const float* __restrict__ bias)
{
    const int e    = blockIdx.z;
    const int cnt  = g_cnt[e];
    const int row0 = blockIdx.x * BM;
    if (row0 >= cnt) return;
    const int col0 = blockIdx.y * BN;

    extern __shared__ float sm[];
    float* As = sm;                    // [STAGES][BM][ASTR]
    float* Bs = sm + STAGES * ASZ;     // [STAGES][BK][BSTR]

    const int tid  = threadIdx.x;
    const int lane = tid & 31;
    const int warp = tid >> 5;
    const int wm   = warp & 1;         // 2 warps along M (64 rows)
    const int wn   = warp >> 1;        // 4 warps along N (32 cols)

    // --- A loader: row ar (2 threads/row), 4 chunks of 16B each ---
    const int ar  = tid >> 1;          // 0..127
    const int ac0 = (tid & 1) * 16;    // float offset 0 or 16
    const float* ap;
    if (G1) {
        const int tok = g_list[e * Tn + row0 + ar] >> 1;
        ap = g_xt + (size_t)tok * KD;
    } else {
        ap = g_h + ((size_t)e * Tn + row0 + ar) * KD;
    }

    // --- B loader: rows brow+8j (j=0..3), 16B chunk at bc4 ---
    const int brow = tid >> 5;         // 0..7
    const int bc4  = (tid & 31) * 4;   // 0..124
    const float* Wp = W + (size_t)e * KD * N + col0 + bc4;

    float acc[4][4][4];
#pragma unroll
    for (int mi = 0; mi < 4; mi++)
#pragma unroll
        for (int ni = 0; ni < 4; ni++)
#pragma unroll
            for (int j = 0; j < 4; j++) acc[mi][ni][j] = 0.f;

    auto load_stage = [&](int s, int kt) {
        float* as = As + s * ASZ;
        float* bs = Bs + s * BSZ;
        const int kg = kt * BK;
#pragma unroll
        for (int j = 0; j < 4; j++) {
            cp16f(as + ar * ASTR + ac0 + j * 4, ap + kg + ac0 + j * 4);
            cp16f(bs + (brow + 8 * j) * BSTR + bc4,
                  Wp + (size_t)(kg + brow + 8 * j) * N);
        }
    };

    auto compute = [&](int s) {
        const float* as = As + s * ASZ;
        const float* bs = Bs + s * BSZ;
#pragma unroll
        for (int g = 0; g < 4; g++) {              // four k8 steps per BK=32
            const int k = g * 8 + (lane & 3);
            uint32_t Af[4][4];
#pragma unroll
            for (int mi = 0; mi < 4; mi++) {
                const int r = wm * 64 + mi * 16 + (lane >> 2);
                const float* p = as + r * ASTR + k;
                Af[mi][0] = __float_as_uint(p[0]);            // (r,   k)
                Af[mi][1] = __float_as_uint(p[8 * ASTR]);     // (r+8, k)
                Af[mi][2] = __float_as_uint(p[4]);            // (r,   k+4)
                Af[mi][3] = __float_as_uint(p[8 * ASTR + 4]); // (r+8, k+4)
            }
            uint32_t Bf[4][2];
#pragma unroll
            for (int ni = 0; ni < 4; ni++) {
                const int c = wn * 32 + ni * 8 + (lane >> 2);
                const float* p = bs + k * BSTR + c;
                Bf[ni][0] = f2tf_u(p[0]);                     // (k,   c)
                Bf[ni][1] = f2tf_u(p[4 * BSTR]);              // (k+4, c)
            }
#pragma unroll
            for (int mi = 0; mi < 4; mi++)
#pragma unroll
                for (int ni = 0; ni < 4; ni++)
                    mma8(acc[mi][ni], Af[mi], Bf[ni]);
        }
    };

    constexpr int KT = KD / BK;
#pragma unroll
    for (int s = 0; s < STAGES - 1; s++) {
        load_stage(s, s);
        asm volatile("cp.async.commit_group;");
    }
    for (int kt = 0; kt < KT; kt++) {
        asm volatile("cp.async.wait_group 1;" ::: "memory");
        __syncthreads();
        const int nt = kt + STAGES - 1;
        if (nt < KT) load_stage(nt % STAGES, nt);
        asm volatile("cp.async.commit_group;");
        compute(kt % STAGES);
    }

    // ------------------------------- epilogue -------------------------------
    const float* bp = bias + (size_t)e * N + col0;
    float2 bv[4];
#pragma unroll
    for (int ni = 0; ni < 4; ni++) {
        const int c = wn * 32 + ni * 8 + 2 * (lane & 3);
        bv[ni] = *(const float2*)(bp + c);
    }
#pragma unroll
    for (int mi = 0; mi < 4; mi++) {
#pragma unroll
        for (int h = 0; h < 2; h++) {
            const int r = row0 + wm * 64 + mi * 16 + (lane >> 2) + h * 8;
            if (r >= cnt) continue;
            float* op;
            if (G1) {
                op = g_h + ((size_t)e * Tn + r) * N;      // N == Hh
            } else {
                const int slot = g_list[e * Tn + r];      // token*2 + k
                op = g_y + (size_t)slot * N;              // N == Dd
            }
#pragma unroll
            for (int ni = 0; ni < 4; ni++) {
                const int c = col0 + wn * 32 + ni * 8 + 2 * (lane & 3);
                float v0 = acc[mi][ni][h * 2 + 0] + bv[ni].x;
                float v1 = acc[mi][ni][h * 2 + 1] + bv[ni].y;
                if (G1) {
                    v0 = f2tf_f(fmaxf(v0, 0.f));   // round once for GEMM2 feed
                    v1 = f2tf_f(fmaxf(v1, 0.f));
                }
                *(float2*)(op + c) = make_float2(v0, v1);
            }
        }
    }
}

// ------------------------------------------------------ gated combine -------
__global__ void combine_kernel(float* __restrict__ out) {
    const int idx = blockIdx.x * 256 + threadIdx.x;
    const int t   = idx / (Dd / 4);
    const int c   = idx % (Dd / 4);
    const float gA = g_gate[2 * t];
    const float gB = g_gate[2 * t + 1];
    const float4* y4 = (const float4*)g_y;
    const float4 ya = y4[(size_t)(2 * t) * (Dd / 4) + c];
    const float4 yb = y4[(size_t)(2 * t + 1) * (Dd / 4) + c];
    float4 o;
    o.x = gA * ya.x + gB * yb.x;
    o.y = gA * ya.y + gB * yb.y;
    o.z = gA * ya.z + gB * yb.z;
    o.w = gA * ya.w + gB * yb.w;
    ((float4*)out)[idx] = o;
}

// ---------------------------------------------------------------- launch ----
extern "C" void kernel_launch(void* const* d_in, const int* in_sizes, int n_in,
                              void* d_out, int out_size) {
    const float* x  = (const float*)d_in[0];   // (B,N,D)
    const float* wg = (const float*)d_in[1];   // (D,E)
    const float* bg = (const float*)d_in[2];   // (E,)
    const float* w1 = (const float*)d_in[3];   // (E,D,H)
    const float* b1 = (const float*)d_in[4];   // (E,H)
    const float* w2 = (const float*)d_in[5];   // (E,H,D)
    const float* b2 = (const float*)d_in[6];   // (E,D)
    float* out = (float*)d_out;

    const int smem_bytes = SMEM_FLOATS * (int)sizeof(float);   // 107520
    cudaFuncSetAttribute(moe_gemm<Hh, Dd, true>,
                         cudaFuncAttributeMaxDynamicSharedMemorySize, smem_bytes);
    cudaFuncSetAttribute(moe_gemm<Dd, Hh, false>,
                         cudaFuncAttributeMaxDynamicSharedMemorySize, smem_bytes);

    init_kernel<<<1, 32>>>();
    routing_kernel<<<Tn / 8, 256>>>(x, wg, bg);
    entropy_kernel<<<1, 1024>>>(out, (out_size > Tn * Dd) ? 1 : 0);

    // tf32 pre-round: activations only (weights rounded in-register in GEMM)
    round_x_kernel<<<(Tn * Dd / 4) / 256, 256>>>(x);

    moe_gemm<Hh, Dd, true><<<dim3(Tn / BM, Hh / BN, Ee), 256, smem_bytes>>>(w1, b1);
    moe_gemm<Dd, Hh, false><<<dim3(Tn / BM, Dd / BN, Ee), 256, smem_bytes>>>(w2, b2);
    combine_kernel<<<(Tn * Dd / 4) / 256, 256>>>(out);
}

// round 16
// speedup vs baseline: 2.3479x; 1.1078x over previous
#include <cuda_runtime.h>
#include <stdint.h>
#include <math.h>

// Problem constants: B=2, N=2048 -> T=4096 tokens, D=1024, E=8, H=2048, K=2
#define Tn 4096
#define Dd 1024
#define Ee 8
#define Hh 2048

// GEMM tile config (verified R10 core, 546us): block 128x128, BK=16,
// 8 warps (2m x 4n), warp tile 64x32, 3-stage cp.async, 2 CTAs/SM.
#define BM 128
#define BN 128
#define BK 16
#define STAGES 3
#define ASTR 20                      // A smem row stride (floats)
#define BSTR 136                     // B smem row stride (floats)
#define ASZ (BM * ASTR)              // 2560 floats / stage
#define BSZ (BK * BSTR)              // 2176 floats / stage
#define SMEM_FLOATS (STAGES * (ASZ + BSZ))   // 14208 floats = 56832 B

// ---------------- device scratch (allocation-free rule: __device__ globals) --
__device__ int   g_cnt[Ee];
__device__ int   g_list[Ee * Tn];            // pair slot (= token*2 + k) per expert row
__device__ float g_gate[Tn * 2];
__device__ float g_ent[Tn];
__device__ float g_h[(size_t)Ee * Tn * Hh];  // hidden activations (tf32-rounded)
__device__ float g_xt[(size_t)Tn * Dd];      // x, tf32-rounded (same layout)
__device__ float g_w1r[(size_t)Ee * Dd * Hh];// w1, tf32-rounded (same layout)
__device__ float g_w2r[(size_t)Ee * Hh * Dd];// w2, tf32-rounded (same layout)

// -------------------------------------------------------------- helpers -----
__device__ __forceinline__ float f2tf_f(float x) {
    uint32_t r;
    asm("cvt.rna.tf32.f32 %0, %1;" : "=r"(r) : "f"(x));
    return __uint_as_float(r);
}
__device__ __forceinline__ void cp16(float* s, const float* g) {
    uint32_t sa = (uint32_t)__cvta_generic_to_shared(s);
    asm volatile("cp.async.cg.shared.global [%0], [%1], 16;" :: "r"(sa), "l"(g));
}
__device__ __forceinline__ void mma8(float* c, const uint32_t* a, const uint32_t* b) {
    asm volatile(
        "mma.sync.aligned.m16n8k8.row.col.f32.tf32.tf32.f32 "
        "{%0,%1,%2,%3}, {%4,%5,%6,%7}, {%8,%9}, {%0,%1,%2,%3};"
        : "+f"(c[0]), "+f"(c[1]), "+f"(c[2]), "+f"(c[3])
        : "r"(a[0]), "r"(a[1]), "r"(a[2]), "r"(a[3]), "r"(b[0]), "r"(b[1]));
}

// ---------------------------------------------------------------- init ------
__global__ void init_kernel() {
    if (threadIdx.x < Ee) g_cnt[threadIdx.x] = 0;
}

// ------------------------------------- zero output (for atomic combine) -----
__global__ void zero_out_kernel(float* __restrict__ out) {
    const int idx = blockIdx.x * 256 + threadIdx.x;       // over Tn*Dd/4
    ((float4*)out)[idx] = make_float4(0.f, 0.f, 0.f, 0.f);
}

// ------------------------------- routing (+ fused tf32 round of x) ----------
__global__ void routing_kernel(const float* __restrict__ x,
                               const float* __restrict__ wg,
                               const float* __restrict__ bg) {
    const int t    = blockIdx.x * 8 + (threadIdx.x >> 5);
    const int lane = threadIdx.x & 31;
    if (t >= Tn) return;

    float acc[Ee];
#pragma unroll
    for (int e = 0; e < Ee; e++) acc[e] = 0.f;

    const float* xr = x + (size_t)t * Dd;
    float* xo = g_xt + (size_t)t * Dd;
    for (int c = lane; c < Dd; c += 32) {
        const float xv = xr[c];
        xo[c] = f2tf_f(xv);                          // fused pre-round store
        const float4* w4 = reinterpret_cast<const float4*>(wg + (size_t)c * Ee);
        const float4 a = w4[0];
        const float4 b = w4[1];
        acc[0] += xv * a.x; acc[1] += xv * a.y; acc[2] += xv * a.z; acc[3] += xv * a.w;
        acc[4] += xv * b.x; acc[5] += xv * b.y; acc[6] += xv * b.z; acc[7] += xv * b.w;
    }
#pragma unroll
    for (int off = 16; off; off >>= 1) {
#pragma unroll
        for (int e = 0; e < Ee; e++)
            acc[e] += __shfl_xor_sync(0xffffffffu, acc[e], off);
    }

    if (lane == 0) {
        float l[Ee];
#pragma unroll
        for (int e = 0; e < Ee; e++) l[e] = acc[e] + bg[e];

        // top-2 (ties -> lowest index, matching jax.lax.top_k)
        int i0 = 0; float v0 = l[0];
#pragma unroll
        for (int e = 1; e < Ee; e++) if (l[e] > v0) { v0 = l[e]; i0 = e; }
        int i1 = -1; float v1 = -3.4e38f;
#pragma unroll
        for (int e = 0; e < Ee; e++)
            if (e != i0 && l[e] > v1) { v1 = l[e]; i1 = e; }

        const float e1 = expf(v1 - v0);
        const float inv = 1.f / (1.f + e1);
        const float gv0 = inv;
        const float gv1 = e1 * inv;

        g_ent[t] = -(gv0 * logf(fmaxf(gv0, 1e-8f)) +
                     gv1 * logf(fmaxf(gv1, 1e-8f)));

        int p0 = atomicAdd(&g_cnt[i0], 1);
        g_list[i0 * Tn + p0] = t * 2 + 0;
        g_gate[t * 2 + 0] = gv0;

        int p1 = atomicAdd(&g_cnt[i1], 1);
        g_list[i1 * Tn + p1] = t * 2 + 1;
        g_gate[t * 2 + 1] = gv1;
    }
}

// ------------------------------------------------- entropy (deterministic) --
__global__ void entropy_kernel(float* __restrict__ out, int do_write) {
    __shared__ float sh[1024];
    const int t = threadIdx.x;
    float s = 0.f;
    for (int i = t; i < Tn; i += 1024) s += g_ent[i];
    sh[t] = s;
    __syncthreads();
    for (int o = 512; o; o >>= 1) {
        if (t < o) sh[t] += sh[t + o];
        __syncthreads();
    }
    if (t == 0 && do_write) out[(size_t)Tn * Dd] = sh[0] / (float)Tn;
}

// --------------------------------------------- tf32 pre-round: weights ------
__global__ void round_w1_kernel(const float* __restrict__ w1) {
    const size_t idx = (size_t)blockIdx.x * 256 + threadIdx.x;   // over E*D*H/4
    float4 v = ((const float4*)w1)[idx];
    v.x = f2tf_f(v.x); v.y = f2tf_f(v.y); v.z = f2tf_f(v.z); v.w = f2tf_f(v.w);
    ((float4*)g_w1r)[idx] = v;
}
__global__ void round_w2_kernel(const float* __restrict__ w2) {
    const size_t idx = (size_t)blockIdx.x * 256 + threadIdx.x;   // over E*H*D/4
    float4 v = ((const float4*)w2)[idx];
    v.x = f2tf_f(v.x); v.y = f2tf_f(v.y); v.z = f2tf_f(v.z); v.w = f2tf_f(v.w);
    ((float4*)g_w2r)[idx] = v;
}

// ----------------------------------------------------- tf32 grouped GEMM ----
// C[r, c] = A[r, :] @ W_e[:, c] + bias_e[c]
//   G1: A gathered from g_xt via g_list; out = relu+round -> g_h
//  !G1: A from g_h; out = gate * (C) atomically accumulated into `out`
template<int N, int KD, bool G1>
__global__ __launch_bounds__(256, 2)
void moe_gemm(const float* __restrict__ bias, float* __restrict__ outp)
{
    const int e    = blockIdx.z;
    const int cnt  = g_cnt[e];
    const int row0 = blockIdx.x * BM;
    if (row0 >= cnt) return;
    const int col0 = blockIdx.y * BN;

    extern __shared__ float sm[];
    float* As = sm;                    // [STAGES][BM][ASTR]
    float* Bs = sm + STAGES * ASZ;     // [STAGES][BK][BSTR]

    const int tid  = threadIdx.x;
    const int lane = tid & 31;
    const int warp = tid >> 5;
    const int wm   = warp & 1;         // 2 warps along M (64 rows)
    const int wn   = warp >> 1;        // 4 warps along N (32 cols)

    // --- A loader: 2 rows per thread (128 rows x 4 float4 per stage) ---
    const int ar0 = tid >> 2;          // 0..63
    const int ak4 = (tid & 3) * 4;     // k offset within BK (0,4,8,12)
    const float* ap0;
    const float* ap1;
    if (G1) {
        const int t0 = g_list[e * Tn + row0 + ar0] >> 1;
        const int t1 = g_list[e * Tn + row0 + ar0 + 64] >> 1;
        ap0 = g_xt + (size_t)t0 * KD + ak4;
        ap1 = g_xt + (size_t)t1 * KD + ak4;
    } else {
        ap0 = g_h + ((size_t)e * Tn + row0 + ar0) * KD + ak4;
        ap1 = g_h + ((size_t)e * Tn + row0 + ar0 + 64) * KD + ak4;
    }

    // --- B loader: 2 float4 per thread (16 rows x 32 float4 per stage) ---
    const int brow = tid >> 5;         // 0..7, also loads brow+8
    const int bc4  = lane * 4;         // 0..124
    const float* W = G1 ? g_w1r : g_w2r;
    const float* Wp = W + (size_t)e * KD * N + col0 + bc4;

    float acc[4][4][4];
#pragma unroll
    for (int mi = 0; mi < 4; mi++)
#pragma unroll
        for (int ni = 0; ni < 4; ni++)
#pragma unroll
            for (int j = 0; j < 4; j++) acc[mi][ni][j] = 0.f;

    auto load_stage = [&](int s, int kt) {
        float* as = As + s * ASZ;
        float* bs = Bs + s * BSZ;
        const int kg = kt * BK;
        cp16(as + ar0 * ASTR + ak4, ap0 + kg);
        cp16(as + (ar0 + 64) * ASTR + ak4, ap1 + kg);
        cp16(bs + brow * BSTR + bc4,       Wp + (size_t)(kg + brow) * N);
        cp16(bs + (brow + 8) * BSTR + bc4, Wp + (size_t)(kg + brow + 8) * N);
    };

    auto compute = [&](int s) {
        const float* as = As + s * ASZ;
        const float* bs = Bs + s * BSZ;
#pragma unroll
        for (int g = 0; g < 2; g++) {              // two k8 steps per BK=16
            uint32_t Af[4][4];
#pragma unroll
            for (int mi = 0; mi < 4; mi++) {
                const int r = wm * 64 + mi * 16 + (lane >> 2);
                const int k = g * 8 + (lane & 3);
                const float* p = as + r * ASTR + k;
                Af[mi][0] = __float_as_uint(p[0]);            // (r,   k)
                Af[mi][1] = __float_as_uint(p[8 * ASTR]);     // (r+8, k)
                Af[mi][2] = __float_as_uint(p[4]);            // (r,   k+4)
                Af[mi][3] = __float_as_uint(p[8 * ASTR + 4]); // (r+8, k+4)
            }
            uint32_t Bf[4][2];
#pragma unroll
            for (int ni = 0; ni < 4; ni++) {
                const int c = wn * 32 + ni * 8 + (lane >> 2);
                const int k = g * 8 + (lane & 3);
                const float* p = bs + k * BSTR + c;
                Bf[ni][0] = __float_as_uint(p[0]);            // (k,   c)
                Bf[ni][1] = __float_as_uint(p[4 * BSTR]);     // (k+4, c)
            }
#pragma unroll
            for (int mi = 0; mi < 4; mi++)
#pragma unroll
                for (int ni = 0; ni < 4; ni++)
                    mma8(acc[mi][ni], Af[mi], Bf[ni]);
        }
    };

    constexpr int KT = KD / BK;
#pragma unroll
    for (int s = 0; s < STAGES - 1; s++) {
        load_stage(s, s);
        asm volatile("cp.async.commit_group;");
    }
    for (int kt = 0; kt < KT; kt++) {
        asm volatile("cp.async.wait_group 1;" ::: "memory");
        __syncthreads();
        const int nt = kt + STAGES - 1;
        if (nt < KT) load_stage(nt % STAGES, nt);
        asm volatile("cp.async.commit_group;");
        compute(kt % STAGES);
    }

    // ------------------------------- epilogue -------------------------------
    const float* bp = bias + (size_t)e * N + col0;
    float2 bv[4];
#pragma unroll
    for (int ni = 0; ni < 4; ni++) {
        const int c = wn * 32 + ni * 8 + 2 * (lane & 3);
        bv[ni] = *(const float2*)(bp + c);
    }
#pragma unroll
    for (int mi = 0; mi < 4; mi++) {
#pragma unroll
        for (int h = 0; h < 2; h++) {
            const int r = row0 + wm * 64 + mi * 16 + (lane >> 2) + h * 8;
            if (r >= cnt) continue;
            if (G1) {
                float* op = g_h + ((size_t)e * Tn + r) * N;
#pragma unroll
                for (int ni = 0; ni < 4; ni++) {
                    const int c = col0 + wn * 32 + ni * 8 + 2 * (lane & 3);
                    float v0 = acc[mi][ni][h * 2 + 0] + bv[ni].x;
                    float v1 = acc[mi][ni][h * 2 + 1] + bv[ni].y;
                    v0 = f2tf_f(fmaxf(v0, 0.f));   // round once for GEMM2 feed
                    v1 = f2tf_f(fmaxf(v1, 0.f));
                    *(float2*)(op + c) = make_float2(v0, v1);
                }
            } else {
                // fused gated combine: out[t, c] += gate * (acc + b2)
                // deterministic: out zero-initialized; exactly 2 commutative
                // float adds land on each element.
                const int slot = g_list[e * Tn + r];   // token*2 + k
                const float gv = g_gate[slot];
                float* op = outp + (size_t)(slot >> 1) * N;
#pragma unroll
                for (int ni = 0; ni < 4; ni++) {
                    const int c = col0 + wn * 32 + ni * 8 + 2 * (lane & 3);
                    atomicAdd(op + c,     gv * (acc[mi][ni][h * 2 + 0] + bv[ni].x));
                    atomicAdd(op + c + 1, gv * (acc[mi][ni][h * 2 + 1] + bv[ni].y));
                }
            }
        }
    }
}

// ---------------------------------------------------------------- launch ----
extern "C" void kernel_launch(void* const* d_in, const int* in_sizes, int n_in,
                              void* d_out, int out_size) {
    const float* x  = (const float*)d_in[0];   // (B,N,D)
    const float* wg = (const float*)d_in[1];   // (D,E)
    const float* bg = (const float*)d_in[2];   // (E,)
    const float* w1 = (const float*)d_in[3];   // (E,D,H)
    const float* b1 = (const float*)d_in[4];   // (E,H)
    const float* w2 = (const float*)d_in[5];   // (E,H,D)
    const float* b2 = (const float*)d_in[6];   // (E,D)
    float* out = (float*)d_out;

    const int smem_bytes = SMEM_FLOATS * (int)sizeof(float);   // 56832
    cudaFuncSetAttribute(moe_gemm<Hh, Dd, true>,
                         cudaFuncAttributeMaxDynamicSharedMemorySize, smem_bytes);
    cudaFuncSetAttribute(moe_gemm<Dd, Hh, false>,
                         cudaFuncAttributeMaxDynamicSharedMemorySize, smem_bytes);

    init_kernel<<<1, 32>>>();
    zero_out_kernel<<<(Tn * Dd / 4) / 256, 256>>>(out);
    routing_kernel<<<Tn / 8, 256>>>(x, wg, bg);       // also writes g_xt
    entropy_kernel<<<1, 1024>>>(out, (out_size > Tn * Dd) ? 1 : 0);

    // tf32 pre-round of weights (elementwise, layout-preserving)
    round_w1_kernel<<<(int)(((size_t)Ee * Dd * Hh / 4) / 256), 256>>>(w1);
    round_w2_kernel<<<(int)(((size_t)Ee * Hh * Dd / 4) / 256), 256>>>(w2);

    moe_gemm<Hh, Dd, true><<<dim3(Tn / BM, Hh / BN, Ee), 256, smem_bytes>>>(b1, out);
    moe_gemm<Dd, Hh, false><<<dim3(Tn / BM, Dd / BN, Ee), 256, smem_bytes>>>(b2, out);
}